// round 1
// baseline (speedup 1.0000x reference)
#include <cuda_runtime.h>
#include <cuda_bf16.h>

#define NNODES 100000
#define DIM    128

// Scratch (allocation-free rule: __device__ globals).
__device__ float g_h[(size_t)NNODES * DIM];    // GEMM output per layer
__device__ float g_agg[(size_t)NNODES * DIM];  // aggregation buffer / next-layer input
__device__ float g_dinv[NNODES];               // deg -> rsqrt(deg)

// ---------------- degree kernels ----------------
__global__ void deg_init_kernel(float* __restrict__ deg, int n) {
    int i = blockIdx.x * blockDim.x + threadIdx.x;
    if (i < n) deg[i] = 1.0f;  // self-loop
}

__global__ void deg_acc_kernel(const int* __restrict__ dst, float* __restrict__ deg, int E) {
    int e = blockIdx.x * blockDim.x + threadIdx.x;
    if (e < E) atomicAdd(&deg[dst[e]], 1.0f);
}

__global__ void deg_rsqrt_kernel(float* __restrict__ deg, int n) {
    int i = blockIdx.x * blockDim.x + threadIdx.x;
    if (i < n) deg[i] = rsqrtf(deg[i]);
}

// ---------------- SGEMM: C[M,128] = A[M,128] @ B[128,128] ----------------
// BM=128, BN=128, BK=8, 256 threads, 8x8 register micro-tile per thread.
__global__ __launch_bounds__(256, 2)
void sgemm_128(const float* __restrict__ A, const float* __restrict__ B,
               float* __restrict__ C, int M) {
    __shared__ float As[8][128];   // [k][row] (transposed on store)
    __shared__ float Bs[8][128];   // [k][col]

    const int tid  = threadIdx.x;
    const int row0 = blockIdx.x * 128;

    const int a_row = tid >> 1;          // 0..127
    const int a_col = (tid & 1) * 4;     // 0 or 4  (k-offset)
    const int b_row = tid >> 5;          // 0..7    (k-offset)
    const int b_col = (tid & 31) * 4;    // 0..124

    const int ty = tid >> 4;             // 0..15  -> rows ty*8..ty*8+7
    const int tx = tid & 15;             // 0..15  -> cols tx*8..tx*8+7

    float acc[8][8];
#pragma unroll
    for (int i = 0; i < 8; i++)
#pragma unroll
        for (int j = 0; j < 8; j++) acc[i][j] = 0.0f;

    const int  ga_row = row0 + a_row;
    const bool a_ok   = ga_row < M;

    for (int k0 = 0; k0 < 128; k0 += 8) {
        float4 av = a_ok ? *(const float4*)(A + (size_t)ga_row * DIM + k0 + a_col)
                         : make_float4(0.f, 0.f, 0.f, 0.f);
        As[a_col + 0][a_row] = av.x;
        As[a_col + 1][a_row] = av.y;
        As[a_col + 2][a_row] = av.z;
        As[a_col + 3][a_row] = av.w;

        *(float4*)(&Bs[b_row][b_col]) =
            *(const float4*)(B + (size_t)(k0 + b_row) * DIM + b_col);

        __syncthreads();

#pragma unroll
        for (int k = 0; k < 8; k++) {
            float a[8], b[8];
            *(float4*)(a)     = *(const float4*)(&As[k][ty * 8]);
            *(float4*)(a + 4) = *(const float4*)(&As[k][ty * 8 + 4]);
            *(float4*)(b)     = *(const float4*)(&Bs[k][tx * 8]);
            *(float4*)(b + 4) = *(const float4*)(&Bs[k][tx * 8 + 4]);
#pragma unroll
            for (int i = 0; i < 8; i++)
#pragma unroll
                for (int j = 0; j < 8; j++)
                    acc[i][j] += a[i] * b[j];
        }
        __syncthreads();
    }

#pragma unroll
    for (int i = 0; i < 8; i++) {
        int r = row0 + ty * 8 + i;
        if (r < M) {
            *(float4*)(C + (size_t)r * DIM + tx * 8) =
                make_float4(acc[i][0], acc[i][1], acc[i][2], acc[i][3]);
            *(float4*)(C + (size_t)r * DIM + tx * 8 + 4) =
                make_float4(acc[i][4], acc[i][5], acc[i][6], acc[i][7]);
        }
    }
}

// ---------------- aggregation init: agg = bias + h * dinv^2 (self loop) ----------------
__global__ void agg_init_kernel(const float* __restrict__ h, const float* __restrict__ bias,
                                const float* __restrict__ dinv, float* __restrict__ agg,
                                int n) {
    long idx = (long)blockIdx.x * blockDim.x + threadIdx.x;  // one float4 each
    if (idx >= (long)n * (DIM / 4)) return;
    int node = (int)(idx >> 5);
    int c4   = (int)(idx & 31) * 4;
    float di = dinv[node];
    float s  = di * di;
    float4 v  = *(const float4*)(h + (size_t)node * DIM + c4);
    float4 bb = *(const float4*)(bias + c4);
    float4 r;
    r.x = fmaf(v.x, s, bb.x);
    r.y = fmaf(v.y, s, bb.y);
    r.z = fmaf(v.z, s, bb.z);
    r.w = fmaf(v.w, s, bb.w);
    *(float4*)(agg + (size_t)node * DIM + c4) = r;
}

// ---------------- edge scatter: agg[dst] += h[src] * dinv[src]*dinv[dst] ----------------
// One warp per edge; lane handles 4 features.
__global__ void scatter_kernel(const float* __restrict__ h, const int* __restrict__ src,
                               const int* __restrict__ dst, const float* __restrict__ dinv,
                               float* __restrict__ agg, int E) {
    long idx = (long)blockIdx.x * blockDim.x + threadIdx.x;
    int  e   = (int)(idx >> 5);
    int  ln  = (int)(idx & 31);
    if (e >= E) return;
    int   s   = src[e];
    int   d   = dst[e];
    float nrm = dinv[s] * dinv[d];
    float4 v = *(const float4*)(h + (size_t)s * DIM + ln * 4);
    float* o = agg + (size_t)d * DIM + ln * 4;
    atomicAdd(o + 0, v.x * nrm);
    atomicAdd(o + 1, v.y * nrm);
    atomicAdd(o + 2, v.z * nrm);
    atomicAdd(o + 3, v.w * nrm);
}

// ---------------- relu ----------------
__global__ void relu_kernel(float* __restrict__ a, int n) {
    long idx = (long)blockIdx.x * blockDim.x + threadIdx.x;
    if (idx >= (long)n * (DIM / 4)) return;
    float4 v = ((float4*)a)[idx];
    v.x = fmaxf(v.x, 0.f);
    v.y = fmaxf(v.y, 0.f);
    v.z = fmaxf(v.z, 0.f);
    v.w = fmaxf(v.w, 0.f);
    ((float4*)a)[idx] = v;
}

extern "C" void kernel_launch(void* const* d_in, const int* in_sizes, int n_in,
                              void* d_out, int out_size) {
    const float* x  = (const float*)d_in[0];
    const int*   ei = (const int*)d_in[1];
    const float* W1 = (const float*)d_in[2];
    const float* b1 = (const float*)d_in[3];
    const float* W2 = (const float*)d_in[4];
    const float* b2 = (const float*)d_in[5];
    const float* W3 = (const float*)d_in[6];
    const float* b3 = (const float*)d_in[7];
    float*       out = (float*)d_out;

    const int N = in_sizes[0] / DIM;
    const int E = in_sizes[1] / 2;
    const int* src = ei;
    const int* dst = ei + E;

    float *h, *agg, *dinv;
    cudaGetSymbolAddress((void**)&h,    g_h);
    cudaGetSymbolAddress((void**)&agg,  g_agg);
    cudaGetSymbolAddress((void**)&dinv, g_dinv);

    const int TB = 256;
    const int n_blk   = (N + TB - 1) / TB;
    const int e_blk   = (E + TB - 1) / TB;
    const int gemm_g  = (N + 127) / 128;
    const long nd4    = (long)N * (DIM / 4);
    const int agg_blk = (int)((nd4 + TB - 1) / TB);
    const long sth    = (long)E * 32;
    const int sc_blk  = (int)((sth + TB - 1) / TB);

    // degrees (self-loops included), then dinv = rsqrt(deg)
    deg_init_kernel<<<n_blk, TB>>>(dinv, N);
    deg_acc_kernel<<<e_blk, TB>>>(dst, dinv, E);
    deg_rsqrt_kernel<<<n_blk, TB>>>(dinv, N);

    // layer 1: h = x@W1 ; agg = b1 + self + edges ; relu
    sgemm_128<<<gemm_g, 256>>>(x, W1, h, N);
    agg_init_kernel<<<agg_blk, TB>>>(h, b1, dinv, agg, N);
    scatter_kernel<<<sc_blk, TB>>>(h, src, dst, dinv, agg, E);
    relu_kernel<<<agg_blk, TB>>>(agg, N);

    // layer 2
    sgemm_128<<<gemm_g, 256>>>(agg, W2, h, N);
    agg_init_kernel<<<agg_blk, TB>>>(h, b2, dinv, agg, N);
    scatter_kernel<<<sc_blk, TB>>>(h, src, dst, dinv, agg, E);
    relu_kernel<<<agg_blk, TB>>>(agg, N);

    // layer 3 -> d_out (no relu)
    sgemm_128<<<gemm_g, 256>>>(agg, W3, h, N);
    agg_init_kernel<<<agg_blk, TB>>>(h, b3, dinv, out, N);
    scatter_kernel<<<sc_blk, TB>>>(h, src, dst, dinv, out, E);
}

// round 2
// speedup vs baseline: 3.0561x; 3.0561x over previous
#include <cuda_runtime.h>
#include <cuda_bf16.h>

#define NNODES 100000
#define EMAX   1600000
#define DIM    128

// Scratch (__device__ globals: allocation-free rule)
__device__ float g_h[(size_t)NNODES * DIM];    // GEMM output per layer
__device__ float g_agg[(size_t)NNODES * DIM];  // aggregation output / next input
__device__ float g_dinv[NNODES];               // rsqrt(deg)
__device__ int   g_deg[NNODES];                // in-degree (excl self-loop)
__device__ int   g_cnt[NNODES];                // fill counters
__device__ int   g_rowptr[NNODES + 1];         // CSR row pointers (by dst)
__device__ int   g_bsum[256];                  // scan block sums
__device__ int   g_csr_src[EMAX];              // CSR src node per edge
__device__ float g_csr_coef[EMAX];             // per-edge norm coefficient

// ---------------- CSR build ----------------
__global__ void zero2_kernel(int* __restrict__ a, int* __restrict__ b, int n) {
    int i = blockIdx.x * blockDim.x + threadIdx.x;
    if (i < n) { a[i] = 0; b[i] = 0; }
}

__global__ void deg_acc_kernel(const int* __restrict__ dst, int* __restrict__ deg, int E) {
    int e = blockIdx.x * blockDim.x + threadIdx.x;
    if (e < E) atomicAdd(&deg[dst[e]], 1);
}

__global__ void dinv_kernel(const int* __restrict__ deg, float* __restrict__ dinv, int n) {
    int i = blockIdx.x * blockDim.x + threadIdx.x;
    if (i < n) dinv[i] = rsqrtf((float)(deg[i] + 1));  // +1 self-loop
}

// exclusive scan, chunk = 1024 elems / block of 256 threads (4 elems each)
__global__ void scan1_kernel(const int* __restrict__ in, int* __restrict__ out,
                             int* __restrict__ bsum, int n) {
    __shared__ int sh[256];
    int t  = threadIdx.x;
    int i0 = blockIdx.x * 1024 + t * 4;
    int v[4];
#pragma unroll
    for (int k = 0; k < 4; k++) v[k] = (i0 + k < n) ? in[i0 + k] : 0;
    int s = v[0] + v[1] + v[2] + v[3];
    sh[t] = s;
    __syncthreads();
#pragma unroll
    for (int off = 1; off < 256; off <<= 1) {
        int x = (t >= off) ? sh[t - off] : 0;
        __syncthreads();
        sh[t] += x;
        __syncthreads();
    }
    int excl = sh[t] - s;  // exclusive prefix of this thread within chunk
    int run = excl;
#pragma unroll
    for (int k = 0; k < 4; k++) {
        if (i0 + k < n) out[i0 + k] = run;
        run += v[k];
    }
    if (t == 255) bsum[blockIdx.x] = sh[255];
}

__global__ void scan2_kernel(int* __restrict__ bsum, int nch, int* __restrict__ rowptr,
                             int n, int E) {
    if (blockIdx.x == 0 && threadIdx.x == 0) {
        int run = 0;
        for (int i = 0; i < nch; i++) { int t = bsum[i]; bsum[i] = run; run += t; }
        rowptr[n] = E;
    }
}

__global__ void scan3_kernel(int* __restrict__ rowptr, const int* __restrict__ bsum, int n) {
    int i = blockIdx.x * blockDim.x + threadIdx.x;
    if (i < n) rowptr[i] += bsum[i >> 10];
}

__global__ void fill_kernel(const int* __restrict__ src, const int* __restrict__ dst,
                            const int* __restrict__ rowptr, int* __restrict__ cnt,
                            const float* __restrict__ dinv,
                            int* __restrict__ csr_src, float* __restrict__ csr_coef, int E) {
    int e = blockIdx.x * blockDim.x + threadIdx.x;
    if (e >= E) return;
    int s = src[e], d = dst[e];
    int pos = rowptr[d] + atomicAdd(&cnt[d], 1);
    csr_src[pos]  = s;
    csr_coef[pos] = dinv[s] * dinv[d];
}

// ---------------- SGEMM: C[M,128] = A[M,128] @ B[128,128] ----------------
__global__ __launch_bounds__(256, 2)
void sgemm_128(const float* __restrict__ A, const float* __restrict__ B,
               float* __restrict__ C, int M) {
    __shared__ float As[8][128];
    __shared__ float Bs[8][128];

    const int tid  = threadIdx.x;
    const int row0 = blockIdx.x * 128;

    const int a_row = tid >> 1;
    const int a_col = (tid & 1) * 4;
    const int b_row = tid >> 5;
    const int b_col = (tid & 31) * 4;
    const int ty = tid >> 4;
    const int tx = tid & 15;

    float acc[8][8];
#pragma unroll
    for (int i = 0; i < 8; i++)
#pragma unroll
        for (int j = 0; j < 8; j++) acc[i][j] = 0.0f;

    const int  ga_row = row0 + a_row;
    const bool a_ok   = ga_row < M;

    for (int k0 = 0; k0 < 128; k0 += 8) {
        float4 av = a_ok ? *(const float4*)(A + (size_t)ga_row * DIM + k0 + a_col)
                         : make_float4(0.f, 0.f, 0.f, 0.f);
        As[a_col + 0][a_row] = av.x;
        As[a_col + 1][a_row] = av.y;
        As[a_col + 2][a_row] = av.z;
        As[a_col + 3][a_row] = av.w;

        *(float4*)(&Bs[b_row][b_col]) =
            *(const float4*)(B + (size_t)(k0 + b_row) * DIM + b_col);

        __syncthreads();

#pragma unroll
        for (int k = 0; k < 8; k++) {
            float a[8], b[8];
            *(float4*)(a)     = *(const float4*)(&As[k][ty * 8]);
            *(float4*)(a + 4) = *(const float4*)(&As[k][ty * 8 + 4]);
            *(float4*)(b)     = *(const float4*)(&Bs[k][tx * 8]);
            *(float4*)(b + 4) = *(const float4*)(&Bs[k][tx * 8 + 4]);
#pragma unroll
            for (int i = 0; i < 8; i++)
#pragma unroll
                for (int j = 0; j < 8; j++)
                    acc[i][j] += a[i] * b[j];
        }
        __syncthreads();
    }

#pragma unroll
    for (int i = 0; i < 8; i++) {
        int r = row0 + ty * 8 + i;
        if (r < M) {
            *(float4*)(C + (size_t)r * DIM + tx * 8) =
                make_float4(acc[i][0], acc[i][1], acc[i][2], acc[i][3]);
            *(float4*)(C + (size_t)r * DIM + tx * 8 + 4) =
                make_float4(acc[i][4], acc[i][5], acc[i][6], acc[i][7]);
        }
    }
}

// ---------------- fused gather: out[d] = relu?( b + dinv[d]^2*h[d] + sum_e c_e*h[src_e] ) ----------------
// One warp per node; each lane owns 4 features.
template <bool RELU>
__global__ __launch_bounds__(256)
void gather_kernel(const float* __restrict__ h, const float* __restrict__ bias,
                   const int* __restrict__ rowptr, const int* __restrict__ csr_src,
                   const float* __restrict__ csr_coef, const float* __restrict__ dinv,
                   float* __restrict__ out, int n) {
    int warp = (blockIdx.x * blockDim.x + threadIdx.x) >> 5;
    int lane = threadIdx.x & 31;
    if (warp >= n) return;
    const int d = warp;
    const int c4 = lane * 4;

    float di = __ldg(&dinv[d]);
    float s  = di * di;
    float4 self = *(const float4*)(h + (size_t)d * DIM + c4);
    float4 bb   = *(const float4*)(bias + c4);
    float4 acc;
    acc.x = fmaf(self.x, s, bb.x);
    acc.y = fmaf(self.y, s, bb.y);
    acc.z = fmaf(self.z, s, bb.z);
    acc.w = fmaf(self.w, s, bb.w);

    int j   = __ldg(&rowptr[d]);
    int end = __ldg(&rowptr[d + 1]);

    for (; j + 1 < end; j += 2) {
        int   s0 = __ldg(&csr_src[j]);
        int   s1 = __ldg(&csr_src[j + 1]);
        float c0 = __ldg(&csr_coef[j]);
        float c1 = __ldg(&csr_coef[j + 1]);
        float4 v0 = *(const float4*)(h + (size_t)s0 * DIM + c4);
        float4 v1 = *(const float4*)(h + (size_t)s1 * DIM + c4);
        acc.x = fmaf(v0.x, c0, acc.x);
        acc.y = fmaf(v0.y, c0, acc.y);
        acc.z = fmaf(v0.z, c0, acc.z);
        acc.w = fmaf(v0.w, c0, acc.w);
        acc.x = fmaf(v1.x, c1, acc.x);
        acc.y = fmaf(v1.y, c1, acc.y);
        acc.z = fmaf(v1.z, c1, acc.z);
        acc.w = fmaf(v1.w, c1, acc.w);
    }
    if (j < end) {
        int   s0 = __ldg(&csr_src[j]);
        float c0 = __ldg(&csr_coef[j]);
        float4 v0 = *(const float4*)(h + (size_t)s0 * DIM + c4);
        acc.x = fmaf(v0.x, c0, acc.x);
        acc.y = fmaf(v0.y, c0, acc.y);
        acc.z = fmaf(v0.z, c0, acc.z);
        acc.w = fmaf(v0.w, c0, acc.w);
    }

    if (RELU) {
        acc.x = fmaxf(acc.x, 0.f);
        acc.y = fmaxf(acc.y, 0.f);
        acc.z = fmaxf(acc.z, 0.f);
        acc.w = fmaxf(acc.w, 0.f);
    }
    *(float4*)(out + (size_t)d * DIM + c4) = acc;
}

extern "C" void kernel_launch(void* const* d_in, const int* in_sizes, int n_in,
                              void* d_out, int out_size) {
    const float* x  = (const float*)d_in[0];
    const int*   ei = (const int*)d_in[1];
    const float* W1 = (const float*)d_in[2];
    const float* b1 = (const float*)d_in[3];
    const float* W2 = (const float*)d_in[4];
    const float* b2 = (const float*)d_in[5];
    const float* W3 = (const float*)d_in[6];
    const float* b3 = (const float*)d_in[7];
    float*       out = (float*)d_out;

    const int N = in_sizes[0] / DIM;
    const int E = in_sizes[1] / 2;
    const int* src = ei;
    const int* dst = ei + E;

    float *h, *agg, *dinv, *csr_coef;
    int *deg, *cnt, *rowptr, *bsum, *csr_src;
    cudaGetSymbolAddress((void**)&h,        g_h);
    cudaGetSymbolAddress((void**)&agg,      g_agg);
    cudaGetSymbolAddress((void**)&dinv,     g_dinv);
    cudaGetSymbolAddress((void**)&deg,      g_deg);
    cudaGetSymbolAddress((void**)&cnt,      g_cnt);
    cudaGetSymbolAddress((void**)&rowptr,   g_rowptr);
    cudaGetSymbolAddress((void**)&bsum,     g_bsum);
    cudaGetSymbolAddress((void**)&csr_src,  g_csr_src);
    cudaGetSymbolAddress((void**)&csr_coef, g_csr_coef);

    const int TB = 256;
    const int n_blk  = (N + TB - 1) / TB;
    const int e_blk  = (E + TB - 1) / TB;
    const int gemm_g = (N + 127) / 128;
    const int nch    = (N + 1023) / 1024;
    const int gat_blk = (int)(((long)N * 32 + TB - 1) / TB);

    // ---- CSR build (by destination) ----
    zero2_kernel<<<n_blk, TB>>>(deg, cnt, N);
    deg_acc_kernel<<<e_blk, TB>>>(dst, deg, E);
    dinv_kernel<<<n_blk, TB>>>(deg, dinv, N);
    scan1_kernel<<<nch, 256>>>(deg, rowptr, bsum, N);
    scan2_kernel<<<1, 32>>>(bsum, nch, rowptr, N, E);
    scan3_kernel<<<n_blk, TB>>>(rowptr, bsum, N);
    fill_kernel<<<e_blk, TB>>>(src, dst, rowptr, cnt, dinv, csr_src, csr_coef, E);

    // ---- layer 1 ----
    sgemm_128<<<gemm_g, 256>>>(x, W1, h, N);
    gather_kernel<true><<<gat_blk, TB>>>(h, b1, rowptr, csr_src, csr_coef, dinv, agg, N);
    // ---- layer 2 ----
    sgemm_128<<<gemm_g, 256>>>(agg, W2, h, N);
    gather_kernel<true><<<gat_blk, TB>>>(h, b2, rowptr, csr_src, csr_coef, dinv, agg, N);
    // ---- layer 3 -> d_out ----
    sgemm_128<<<gemm_g, 256>>>(agg, W3, h, N);
    gather_kernel<false><<<gat_blk, TB>>>(h, b3, rowptr, csr_src, csr_coef, dinv, out, N);
}